// round 3
// baseline (speedup 1.0000x reference)
#include <cuda_runtime.h>
#include <cstdint>

#define NN 50000
#define RR 16
#define DD 200
#define EE 400000

#define BM 64
#define TK 8
#define NT 160   // 16 rowgrps x 10 colgrps, 4x20 thread tile

#define NSEG (RR * NN)              // 800000
#define NBLK ((NSEG + 1023) / 1024) // 782

// ---------------- scratch (device globals; no runtime allocation) ----------
__device__ float g_mean[(size_t)RR * NN * DD]; // compact mean rows per (r, pos)
__device__ int   g_cnt[NSEG];                  // per-(r,dst) edge counts
__device__ int   g_cur[NSEG];                  // fill cursors
__device__ int   g_off[NSEG];                  // CSR offsets (exclusive scan)
__device__ int   g_bsum[1024];                 // scan block sums
__device__ int   g_srcids[EE];                 // CSR: src node per edge slot
__device__ int   g_list[NSEG];                 // per-relation active dst list
__device__ int   g_listcnt[RR];                // active count per relation
__device__ float g_h[NN * DD];                 // layer-1 activations

__device__ __forceinline__ void red4(float* p, float4 v) {
    asm volatile("red.global.add.v4.f32 [%0], {%1,%2,%3,%4};"
                 :: "l"(p), "f"(v.x), "f"(v.y), "f"(v.z), "f"(v.w)
                 : "memory");
}

// ---------------- one-time graph preprocessing ------------------------------

__global__ void k_init() {
    int stride = gridDim.x * blockDim.x;
    for (int i = blockIdx.x * blockDim.x + threadIdx.x; i < NSEG; i += stride) {
        g_cnt[i] = 0;
        g_cur[i] = 0;
    }
    if (blockIdx.x == 0 && threadIdx.x < RR) g_listcnt[threadIdx.x] = 0;
}

__global__ void k_count(const int* __restrict__ dst, const int* __restrict__ et) {
    int e = blockIdx.x * blockDim.x + threadIdx.x;
    if (e >= EE) return;
    atomicAdd(&g_cnt[et[e] * NN + dst[e]], 1);
}

__global__ void k_scan1() {
    __shared__ int sh[1024];
    int i = blockIdx.x * 1024 + threadIdx.x;
    int v = (i < NSEG) ? g_cnt[i] : 0;
    sh[threadIdx.x] = v;
    __syncthreads();
    #pragma unroll
    for (int d = 1; d < 1024; d <<= 1) {
        int t = (threadIdx.x >= d) ? sh[threadIdx.x - d] : 0;
        __syncthreads();
        sh[threadIdx.x] += t;
        __syncthreads();
    }
    if (i < NSEG) g_off[i] = sh[threadIdx.x] - v;     // exclusive within block
    if (threadIdx.x == 1023) g_bsum[blockIdx.x] = sh[1023];
}

__global__ void k_scan2() {   // single block of 1024
    __shared__ int sh[1024];
    int v = (threadIdx.x < NBLK) ? g_bsum[threadIdx.x] : 0;
    sh[threadIdx.x] = v;
    __syncthreads();
    #pragma unroll
    for (int d = 1; d < 1024; d <<= 1) {
        int t = (threadIdx.x >= d) ? sh[threadIdx.x - d] : 0;
        __syncthreads();
        sh[threadIdx.x] += t;
        __syncthreads();
    }
    g_bsum[threadIdx.x] = sh[threadIdx.x] - v;        // exclusive
}

__global__ void k_scan3() {
    int i = blockIdx.x * 1024 + threadIdx.x;
    if (i < NSEG) g_off[i] += g_bsum[blockIdx.x];
}

__global__ void k_fill(const int* __restrict__ src, const int* __restrict__ dst,
                       const int* __restrict__ et) {
    int e = blockIdx.x * blockDim.x + threadIdx.x;
    if (e >= EE) return;
    int seg = et[e] * NN + dst[e];
    int pos = g_off[seg] + atomicAdd(&g_cur[seg], 1);
    g_srcids[pos] = src[e];
}

__global__ void k_compact() {
    int i = blockIdx.x * blockDim.x + threadIdx.x;
    if (i >= NSEG) return;
    if (g_cnt[i] > 0) {
        int r = i / NN, n = i - r * NN;
        int p = atomicAdd(&g_listcnt[r], 1);
        g_list[r * NN + p] = n;
    }
}

// ---------------- per-layer kernels -----------------------------------------

// one warp per active (r, pos): gather src rows of x, average, write g_mean
__global__ void k_mean(const float* __restrict__ x) {
    int wid = threadIdx.x >> 5, lane = threadIdx.x & 31;
    int p = blockIdx.x * (blockDim.x >> 5) + wid;
    int r = blockIdx.y;
    if (p >= g_listcnt[r]) return;
    int n = g_list[r * NN + p];
    int seg = r * NN + n;
    int o0 = g_off[seg];
    int deg = g_cnt[seg];
    float inv = 1.0f / (float)deg;

    float4 a0 = make_float4(0.f, 0.f, 0.f, 0.f);
    float4 a1 = a0;
    for (int e = 0; e < deg; e++) {
        const float4* xr = (const float4*)(x + (size_t)g_srcids[o0 + e] * DD);
        float4 v = xr[lane];
        a0.x += v.x; a0.y += v.y; a0.z += v.z; a0.w += v.w;
        if (lane < 18) {
            float4 w = xr[lane + 32];
            a1.x += w.x; a1.y += w.y; a1.z += w.z; a1.w += w.w;
        }
    }
    float4* mp = (float4*)(g_mean + ((size_t)r * NN + p) * DD);
    a0.x *= inv; a0.y *= inv; a0.z *= inv; a0.w *= inv;
    mp[lane] = a0;
    if (lane < 18) {
        a1.x *= inv; a1.y *= inv; a1.z *= inv; a1.w *= inv;
        mp[lane + 32] = a1;
    }
}

__global__ void k_relu() {
    float4* h4 = (float4*)g_h;
    const int n4 = NN * DD / 4;
    for (int i = blockIdx.x * blockDim.x + threadIdx.x; i < n4;
         i += gridDim.x * blockDim.x) {
        float4 v = h4[i];
        v.x = fmaxf(v.x, 0.f); v.y = fmaxf(v.y, 0.f);
        v.z = fmaxf(v.z, 0.f); v.w = fmaxf(v.w, 0.f);
        h4[i] = v;
    }
}

// GEMM. REL=false: out[n,:] = A[n,:] @ W + bias   (dense rows, plain store)
//       REL=true : out[g_list[r,p],:] += g_mean[r,p,:] @ W[r]  (red4 accumulate)
template <bool REL>
__global__ __launch_bounds__(NT, 3)
void k_gemm(const float* __restrict__ A,
            const float* __restrict__ W,
            const float* __restrict__ bias,
            float* __restrict__ out) {
    __shared__ float As[TK][BM];
    __shared__ float Bs[TK][DD];

    const int r  = REL ? blockIdx.y : 0;
    const int m0 = blockIdx.x * BM;

    int valid = REL ? (g_listcnt[r] - m0) : (NN - m0);
    if (valid <= 0) return;
    if (valid > BM) valid = BM;

    const int tid = threadIdx.x;
    const float* Ab = REL ? (g_mean + (size_t)r * NN * DD) : A;
    const float* Wr = REL ? (W + (size_t)r * DD * DD) : W;

    const int arow  = tid >> 1;      // A-load row (tid<128)
    const int apart = tid & 1;

    // ---- prefetch tile k0=0 into registers ----
    float4 pa = make_float4(0.f, 0.f, 0.f, 0.f);
    float4 pb0, pb1, pb2;
    if (tid < 128 && arow < valid)
        pa = *(const float4*)(Ab + (size_t)(m0 + arow) * DD + apart * 4);
    {
        const float4* w4 = (const float4*)Wr;  // k0 = 0
        pb0 = w4[tid];
        pb1 = w4[tid + 160];
        if (tid < 80) pb2 = w4[tid + 320];
    }

    float acc[4][20];
    #pragma unroll
    for (int i = 0; i < 4; i++)
        #pragma unroll
        for (int j = 0; j < 20; j++) acc[i][j] = 0.f;

    const int rowgrp = tid / 10;
    const int colgrp = tid - rowgrp * 10;
    const int c0 = colgrp * 20;

    for (int k0 = 0; k0 < DD; k0 += TK) {
        // store prefetched tile to smem
        if (tid < 128) {
            int kb = apart * 4;
            As[kb + 0][arow] = pa.x; As[kb + 1][arow] = pa.y;
            As[kb + 2][arow] = pa.z; As[kb + 3][arow] = pa.w;
        }
        {
            float4* b4 = (float4*)&Bs[0][0];
            b4[tid] = pb0;
            b4[tid + 160] = pb1;
            if (tid < 80) b4[tid + 320] = pb2;
        }
        __syncthreads();

        // prefetch next tile
        int kn = k0 + TK;
        if (kn < DD) {
            pa = make_float4(0.f, 0.f, 0.f, 0.f);
            if (tid < 128 && arow < valid)
                pa = *(const float4*)(Ab + (size_t)(m0 + arow) * DD + kn + apart * 4);
            const float4* w4 = (const float4*)(Wr + (size_t)kn * DD);
            pb0 = w4[tid];
            pb1 = w4[tid + 160];
            if (tid < 80) pb2 = w4[tid + 320];
        }

        // compute
        #pragma unroll
        for (int kk = 0; kk < TK; kk++) {
            float4 a = *(const float4*)&As[kk][rowgrp * 4];
            #pragma unroll
            for (int jj = 0; jj < 5; jj++) {
                int j = jj + colgrp;
                j = (j >= 5) ? (j - 5) : j;           // stagger: kill bank conflicts
                j = (j >= 5) ? (j - 5) : j;
                float4 b = *(const float4*)&Bs[kk][c0 + j * 4];
                acc[0][j*4+0] = fmaf(a.x, b.x, acc[0][j*4+0]);
                acc[0][j*4+1] = fmaf(a.x, b.y, acc[0][j*4+1]);
                acc[0][j*4+2] = fmaf(a.x, b.z, acc[0][j*4+2]);
                acc[0][j*4+3] = fmaf(a.x, b.w, acc[0][j*4+3]);
                acc[1][j*4+0] = fmaf(a.y, b.x, acc[1][j*4+0]);
                acc[1][j*4+1] = fmaf(a.y, b.y, acc[1][j*4+1]);
                acc[1][j*4+2] = fmaf(a.y, b.z, acc[1][j*4+2]);
                acc[1][j*4+3] = fmaf(a.y, b.w, acc[1][j*4+3]);
                acc[2][j*4+0] = fmaf(a.z, b.x, acc[2][j*4+0]);
                acc[2][j*4+1] = fmaf(a.z, b.y, acc[2][j*4+1]);
                acc[2][j*4+2] = fmaf(a.z, b.z, acc[2][j*4+2]);
                acc[2][j*4+3] = fmaf(a.z, b.w, acc[2][j*4+3]);
                acc[3][j*4+0] = fmaf(a.w, b.x, acc[3][j*4+0]);
                acc[3][j*4+1] = fmaf(a.w, b.y, acc[3][j*4+1]);
                acc[3][j*4+2] = fmaf(a.w, b.z, acc[3][j*4+2]);
                acc[3][j*4+3] = fmaf(a.w, b.w, acc[3][j*4+3]);
            }
        }
        __syncthreads();
    }

    // epilogue
    #pragma unroll
    for (int i = 0; i < 4; i++) {
        int row = rowgrp * 4 + i;
        if (row >= valid) continue;
        int n = REL ? g_list[r * NN + m0 + row] : (m0 + row);
        float* op = out + (size_t)n * DD + c0;
        if (REL) {
            #pragma unroll
            for (int j = 0; j < 5; j++) {
                float4 v = make_float4(acc[i][j*4+0], acc[i][j*4+1],
                                       acc[i][j*4+2], acc[i][j*4+3]);
                red4(op + j * 4, v);
            }
        } else {
            #pragma unroll
            for (int j = 0; j < 5; j++) {
                float4 v;
                v.x = acc[i][j*4+0] + bias[c0 + j*4 + 0];
                v.y = acc[i][j*4+1] + bias[c0 + j*4 + 1];
                v.z = acc[i][j*4+2] + bias[c0 + j*4 + 2];
                v.w = acc[i][j*4+3] + bias[c0 + j*4 + 3];
                *(float4*)(op + j * 4) = v;
            }
        }
    }
}

// ---------------- launch -----------------------------------------------------

extern "C" void kernel_launch(void* const* d_in, const int* in_sizes, int n_in,
                              void* d_out, int out_size) {
    const int*   ei    = (const int*)d_in[0];
    const int*   et    = (const int*)d_in[1];
    const float* emb   = (const float*)d_in[2];
    const float* W1    = (const float*)d_in[3];
    const float* root1 = (const float*)d_in[4];
    const float* b1    = (const float*)d_in[5];
    const float* W2    = (const float*)d_in[6];
    const float* root2 = (const float*)d_in[7];
    const float* b2    = (const float*)d_in[8];
    float* out = (float*)d_out;

    const int* src = ei;
    const int* dst = ei + EE;

    float* hptr = nullptr;
    cudaGetSymbolAddress((void**)&hptr, g_h);

    const int mb = (NN + BM - 1) / BM;          // 782
    const int eb = (EE + 255) / 256;
    const int sb = (NSEG + 255) / 256;

    // ---- one-time CSR + compaction (graph is layer-invariant) ----
    k_init<<<1024, 256>>>();
    k_count<<<eb, 256>>>(dst, et);
    k_scan1<<<NBLK, 1024>>>();
    k_scan2<<<1, 1024>>>();
    k_scan3<<<NBLK, 1024>>>();
    k_fill<<<eb, 256>>>(src, dst, et);
    k_compact<<<sb, 256>>>();

    // ---- layer 1 ----
    k_mean<<<dim3((NN + 7) / 8, RR), 256>>>(emb);
    k_gemm<false><<<dim3(mb, 1), NT>>>(emb, root1, b1, hptr);
    k_gemm<true ><<<dim3(mb, RR), NT>>>(nullptr, W1, nullptr, hptr);
    k_relu<<<2048, 256>>>();

    // ---- layer 2 ----
    k_mean<<<dim3((NN + 7) / 8, RR), 256>>>(hptr);
    k_gemm<false><<<dim3(mb, 1), NT>>>(hptr, root2, b2, out);
    k_gemm<true ><<<dim3(mb, RR), NT>>>(nullptr, W2, nullptr, out);
}